// round 11
// baseline (speedup 1.0000x reference)
#include <cuda_runtime.h>
#include <cuda_fp16.h>
#include <math.h>

// ---------------------------------------------------------------------------
// SiamFC head, round 11: occupancy push on corr.
//   H[b,r,j,p] = sum_{c,q} x'[b,c,r-8,j+q-8] * z'[b,c,p,q]   (HMMA f16-acc)
//   out[b,i,j] = 0.001 * sum_p H[b,i+p,j,p]                  (fused via RED)
// corr: 4 rows/CTA, 8 warps (j-tile split 0-6 / 7-12), single-copy smem +
// funnel-shift B-frags, f16->f32 flush every 8 c, RED scatter epilogue.
// ---------------------------------------------------------------------------

__device__ __align__(16) unsigned XG[64 * 64 * 112 * 56];     // x' fp16 half2 words
__device__ __align__(16) unsigned ZA[(64 * 64 + 2) * 128];    // z' in A-frag order (+pad)

// Fast exact-GELU: erf via Abramowitz-Stegun 7.1.26 (|err| <= 1.5e-7 abs).
__device__ __forceinline__ float gelu_fast(float v) {
    float s = fabsf(v) * 0.70710678118654752f;
    float t = __frcp_rn(fmaf(0.3275911f, s, 1.0f));
    float p = fmaf(1.061405429f, t, -1.453152027f);
    p = fmaf(p, t, 1.421413741f);
    p = fmaf(p, t, -0.284496736f);
    p = fmaf(p, t, 0.254829592f);
    p = p * t;
    float erfabs = fmaf(-p, __expf(-s * s), 1.0f);
    float erfs = copysignf(erfabs, v);
    return 0.5f * v * (1.0f + erfs);
}

__device__ __forceinline__ void red_add(float* p, float v) {
    asm volatile("red.global.add.f32 [%0], %1;" :: "l"(p), "f"(v) : "memory");
}

// ---- Kernel A: preprocess x -> XG ---------------------------------------------
__global__ __launch_bounds__(192) void prep_x(const float* __restrict__ x,
                                              const float* __restrict__ wx,
                                              const float* __restrict__ bx) {
    int bc = blockIdx.x;        // b*64 + c
    int c  = bc & 63;
    int tid = threadIdx.x;
    __shared__ __align__(16) float sp[98 * 100];

    float4 z4 = make_float4(0.f, 0.f, 0.f, 0.f);
    for (int i = tid; i < 2450; i += 192) reinterpret_cast<float4*>(sp)[i] = z4;
    __syncthreads();

    {
        int col = (tid < 96) ? tid : tid - 96;
        int rp  = (tid < 96) ? 0 : 1;
        const float* xp = x + (size_t)bc * 9216;
        for (int k = 0; k < 48; ++k) {
            int r = 2 * k + rp;
            sp[(r + 1) * 100 + (col + 1)] = xp[r * 96 + col];
        }
    }
    __syncthreads();

    float w[9];
#pragma unroll
    for (int k = 0; k < 9; ++k) w[k] = __ldg(wx + c * 9 + k);
    float bias = __ldg(bx + c);

    int v4 = tid % 12;
    int r0 = tid / 12;
    int xc0 = v4 * 8;

    uint4* dst = reinterpret_cast<uint4*>(XG + (size_t)bc * (112 * 56));
#pragma unroll 1
    for (int it = 0; it < 6; ++it) {
        int r = r0 + 16 * it;
        float rowv[3][12];
#pragma unroll
        for (int di = 0; di < 3; ++di) {
            const float4* src = reinterpret_cast<const float4*>(sp + (r + di) * 100 + xc0);
            float4 A = src[0], B = src[1], C = src[2];
            rowv[di][0] = A.x; rowv[di][1] = A.y; rowv[di][2]  = A.z; rowv[di][3]  = A.w;
            rowv[di][4] = B.x; rowv[di][5] = B.y; rowv[di][6]  = B.z; rowv[di][7]  = B.w;
            rowv[di][8] = C.x; rowv[di][9] = C.y; rowv[di][10] = C.z; rowv[di][11] = C.w;
        }
        unsigned ow[4];
#pragma unroll
        for (int t = 0; t < 4; ++t) {
            float f[2];
#pragma unroll
            for (int u = 0; u < 2; ++u) {
                int e = 2 * t + u;
                float conv = bias;
#pragma unroll
                for (int di = 0; di < 3; ++di)
#pragma unroll
                    for (int dj = 0; dj < 3; ++dj)
                        conv = fmaf(w[di * 3 + dj], rowv[di][e + dj], conv);
                f[u] = gelu_fast(rowv[1][e + 1] + conv);
            }
            __half2 h = __floats2half2_rn(f[0], f[1]);
            ow[t] = *reinterpret_cast<unsigned*>(&h);
        }
        dst[(r + 8) * 14 + 1 + v4] = make_uint4(ow[0], ow[1], ow[2], ow[3]);
    }
}

// ---- Kernel B: preprocess z -> ZA (A-fragment order) ---------------------------
__global__ __launch_bounds__(256) void prep_z(const float* __restrict__ z,
                                              const float* __restrict__ wz,
                                              const float* __restrict__ bz) {
    int bc = blockIdx.x;
    int c  = bc & 63;
    __shared__ float sp[18 * 18];

    for (int i = threadIdx.x; i < 18 * 18; i += 256) sp[i] = 0.0f;
    __syncthreads();

    int t = threadIdx.x;
    int p = t >> 4, q = t & 15;
    sp[(p + 1) * 18 + (q + 1)] = z[(size_t)bc * 256 + t];
    __syncthreads();

    float conv = __ldg(bz + c);
#pragma unroll
    for (int di = 0; di < 3; ++di)
#pragma unroll
        for (int dj = 0; dj < 3; ++dj)
            conv = fmaf(__ldg(wz + c * 9 + di * 3 + dj), sp[(p + di) * 18 + (q + dj)], conv);
    float val = gelu_fast(sp[(p + 1) * 18 + (q + 1)] + conv);

    int lane = ((p & 7) << 2) | ((q & 7) >> 1);
    int reg  = ((p >> 3) & 1) | (((q >> 3) & 1) << 1);
    int h    = q & 1;
    reinterpret_cast<__half*>(ZA)[((size_t)bc * 32 + lane) * 8 + reg * 2 + h] =
        __float2half(val);
}

// ---- Kernel Z: zero-init out ----------------------------------------------------
__global__ __launch_bounds__(256) void zero_out(float* __restrict__ out, int n4) {
    int t = blockIdx.x * 256 + threadIdx.x;
    float4 z4 = make_float4(0.f, 0.f, 0.f, 0.f);
    if (t < n4) reinterpret_cast<float4*>(out)[t] = z4;
}

// ---- Kernel C: correlation GEMM + fused scatter epilogue ------------------------
// Grid (24, 64), 256 threads = 8 warps. Warp w: row = w&3, j-half = w>>2.
// j-half 0 -> j-tiles 0..6, j-half 1 -> j-tiles 7..12.
__global__ __launch_bounds__(256) void corr(float* __restrict__ out) {
    extern __shared__ unsigned sq[];   // [row(4)][c(64)][word(64)] = 65536 B
    int r0 = 8 + 4 * blockIdx.x, b = blockIdx.y;
    int tid = threadIdx.x, lane = tid & 31, w = tid >> 5;
    int row = w & 3, half = w >> 2;
    int r = r0 + row;
    int jt0 = half * 7;            // 0 or 7

    // Stage 4 rows: zero-fill words 56..63. Plane = 1568 uint4, row = 14 uint4.
    for (int t = tid; t < 4096; t += 256) {
        int rw = t >> 10, g = t & 1023, c = g >> 4, v = g & 15;
        uint4 d = make_uint4(0u, 0u, 0u, 0u);
        if (v < 14)
            d = __ldg(reinterpret_cast<const uint4*>(XG) +
                      (size_t)(b * 64 + c) * 1568 + (size_t)(r0 + rw) * 14 + v);
        reinterpret_cast<uint4*>(sq)[t] = d;
    }
    __syncthreads();

    // Per-lane B-frag addressing
    int nj = lane >> 2;
    int q0 = (lane & 3) << 1;
    int loff = (nj + q0) >> 1;                   // 0..6
    unsigned sh = (unsigned)((nj & 1) << 4);     // funnel shift: 0 or 16
    const unsigned* base_row = sq + (row << 12) + 4 * jt0;  // skip to this half's tiles

    const uint4* zp = reinterpret_cast<const uint4*>(ZA) + (size_t)b * 64 * 32 + lane;

    float facc[7][4];
#pragma unroll
    for (int t = 0; t < 7; ++t)
#pragma unroll
        for (int k = 0; k < 4; ++k) facc[t][k] = 0.0f;

    unsigned hacc[7][2];
#pragma unroll
    for (int t = 0; t < 7; ++t) { hacc[t][0] = 0u; hacc[t][1] = 0u; }

    int ntile = 7 - half;   // 7 for half 0, 6 for half 1 (warp-uniform)

    uint4 a = __ldg(zp);
#pragma unroll 1
    for (int cb = 0; cb < 8; ++cb) {
#pragma unroll
        for (int ci = 0; ci < 8; ++ci) {
            int c = 8 * cb + ci;
            uint4 an = __ldg(zp + (c + 1) * 32);   // ZA padded: safe at c=63
            const unsigned* bc = base_row + (c << 6) + loff;
#pragma unroll
            for (int t = 0; t < 7; ++t) {
                if (t < ntile) {
                    unsigned w0 = bc[4 * t],     w1 = bc[4 * t + 1];
                    unsigned w2 = bc[4 * t + 4], w3 = bc[4 * t + 5];
                    unsigned b0 = __funnelshift_r(w0, w1, sh);
                    unsigned b1 = __funnelshift_r(w2, w3, sh);
                    asm volatile(
                        "mma.sync.aligned.m16n8k16.row.col.f16.f16.f16.f16 "
                        "{%0,%1}, {%2,%3,%4,%5}, {%6,%7}, {%0,%1};"
                        : "+r"(hacc[t][0]), "+r"(hacc[t][1])
                        : "r"(a.x), "r"(a.y), "r"(a.z), "r"(a.w), "r"(b0), "r"(b1));
                }
            }
            a = an;
        }
        // Flush f16 fragments into fp32 accumulators (every 8 c)
#pragma unroll
        for (int t = 0; t < 7; ++t) {
            __half2 h0 = *reinterpret_cast<__half2*>(&hacc[t][0]);
            __half2 h1 = *reinterpret_cast<__half2*>(&hacc[t][1]);
            float2 f0 = __half22float2(h0);
            float2 f1 = __half22float2(h1);
            facc[t][0] += f0.x; facc[t][1] += f0.y;
            facc[t][2] += f1.x; facc[t][3] += f1.y;
            hacc[t][0] = 0u; hacc[t][1] = 0u;
        }
    }

    // Fused epilogue: out[b, r-p, j] += 0.001 * H[p][j]
    int p0 = lane >> 2, jn = (lane & 3) << 1;
    float* ob = out + (size_t)b * 9409;
    int i_hi = r - p0;        // p = p0
    int i_lo = i_hi - 8;      // p = p0 + 8
#pragma unroll
    for (int t = 0; t < 7; ++t) {
        int jt = jt0 + t;
        if (jt < 13) {
            int j = jt * 8 + jn;
            bool j0 = (j <= 96), j1 = (j < 96);
            if (i_hi <= 96) {
                if (j0) red_add(ob + i_hi * 97 + j,     facc[t][0] * 0.001f);
                if (j1) red_add(ob + i_hi * 97 + j + 1, facc[t][1] * 0.001f);
            }
            if (i_lo >= 0) {
                if (j0) red_add(ob + i_lo * 97 + j,     facc[t][2] * 0.001f);
                if (j1) red_add(ob + i_lo * 97 + j + 1, facc[t][3] * 0.001f);
            }
        }
    }
}

// ---- launch -----------------------------------------------------------------------
extern "C" void kernel_launch(void* const* d_in, const int* in_sizes, int n_in,
                              void* d_out, int out_size) {
    const float* z  = (const float*)d_in[0];
    const float* x  = (const float*)d_in[1];
    const float* wz = (const float*)d_in[2];
    const float* bz = (const float*)d_in[3];
    const float* wx = (const float*)d_in[4];
    const float* bx = (const float*)d_in[5];
    float* out = (float*)d_out;

    const int SMEM = 65536;
    cudaFuncSetAttribute(corr, cudaFuncAttributeMaxDynamicSharedMemorySize, SMEM);

    int n4 = out_size / 4;  // 150544
    zero_out<<<(n4 + 255) / 256, 256>>>(out, n4);
    prep_x<<<4096, 192>>>(x, wx, bx);
    prep_z<<<4096, 256>>>(z, wz, bz);
    corr<<<dim3(24, 64), 256, SMEM>>>(out);
}

// round 12
// speedup vs baseline: 1.0478x; 1.0478x over previous
#include <cuda_runtime.h>
#include <cuda_fp16.h>
#include <math.h>

// ---------------------------------------------------------------------------
// SiamFC head, round 12: R10 structure + rolling-pair B-frag loads.
//   H[b,r,j,p] = sum_{c,q} x'[b,c,r-8,j+q-8] * z'[b,c,p,q]   (HMMA f16-acc)
//   out[b,i,j] = 0.001 * sum_p H[b,i+p,j,p]                  (fused via RED)
// corr: 4 rows/CTA (warp = row), 13 j-tiles/warp; B-fragments from 28 LDS.32
// per warp-c (stride-4 pair chain, tile t's b1 pair == tile t+1's b0 pair),
// f16->f32 flush every 8 c, RED scatter epilogue.
// ---------------------------------------------------------------------------

__device__ __align__(16) unsigned XG[64 * 64 * 112 * 56];     // x' fp16 half2 words
__device__ __align__(16) unsigned ZA[(64 * 64 + 2) * 128];    // z' in A-frag order (+pad)

// Fast exact-GELU: erf via Abramowitz-Stegun 7.1.26 (|err| <= 1.5e-7 abs).
__device__ __forceinline__ float gelu_fast(float v) {
    float s = fabsf(v) * 0.70710678118654752f;
    float t = __frcp_rn(fmaf(0.3275911f, s, 1.0f));
    float p = fmaf(1.061405429f, t, -1.453152027f);
    p = fmaf(p, t, 1.421413741f);
    p = fmaf(p, t, -0.284496736f);
    p = fmaf(p, t, 0.254829592f);
    p = p * t;
    float erfabs = fmaf(-p, __expf(-s * s), 1.0f);
    float erfs = copysignf(erfabs, v);
    return 0.5f * v * (1.0f + erfs);
}

__device__ __forceinline__ void red_add(float* p, float v) {
    asm volatile("red.global.add.f32 [%0], %1;" :: "l"(p), "f"(v) : "memory");
}

// ---- Kernel A: preprocess x -> XG ---------------------------------------------
__global__ __launch_bounds__(192) void prep_x(const float* __restrict__ x,
                                              const float* __restrict__ wx,
                                              const float* __restrict__ bx) {
    int bc = blockIdx.x;        // b*64 + c
    int c  = bc & 63;
    int tid = threadIdx.x;
    __shared__ __align__(16) float sp[98 * 100];

    float4 z4 = make_float4(0.f, 0.f, 0.f, 0.f);
    for (int i = tid; i < 2450; i += 192) reinterpret_cast<float4*>(sp)[i] = z4;
    __syncthreads();

    {
        int col = (tid < 96) ? tid : tid - 96;
        int rp  = (tid < 96) ? 0 : 1;
        const float* xp = x + (size_t)bc * 9216;
        for (int k = 0; k < 48; ++k) {
            int r = 2 * k + rp;
            sp[(r + 1) * 100 + (col + 1)] = xp[r * 96 + col];
        }
    }
    __syncthreads();

    float w[9];
#pragma unroll
    for (int k = 0; k < 9; ++k) w[k] = __ldg(wx + c * 9 + k);
    float bias = __ldg(bx + c);

    int v4 = tid % 12;
    int r0 = tid / 12;
    int xc0 = v4 * 8;

    uint4* dst = reinterpret_cast<uint4*>(XG + (size_t)bc * (112 * 56));
#pragma unroll 1
    for (int it = 0; it < 6; ++it) {
        int r = r0 + 16 * it;
        float rowv[3][12];
#pragma unroll
        for (int di = 0; di < 3; ++di) {
            const float4* src = reinterpret_cast<const float4*>(sp + (r + di) * 100 + xc0);
            float4 A = src[0], B = src[1], C = src[2];
            rowv[di][0] = A.x; rowv[di][1] = A.y; rowv[di][2]  = A.z; rowv[di][3]  = A.w;
            rowv[di][4] = B.x; rowv[di][5] = B.y; rowv[di][6]  = B.z; rowv[di][7]  = B.w;
            rowv[di][8] = C.x; rowv[di][9] = C.y; rowv[di][10] = C.z; rowv[di][11] = C.w;
        }
        unsigned ow[4];
#pragma unroll
        for (int t = 0; t < 4; ++t) {
            float f[2];
#pragma unroll
            for (int u = 0; u < 2; ++u) {
                int e = 2 * t + u;
                float conv = bias;
#pragma unroll
                for (int di = 0; di < 3; ++di)
#pragma unroll
                    for (int dj = 0; dj < 3; ++dj)
                        conv = fmaf(w[di * 3 + dj], rowv[di][e + dj], conv);
                f[u] = gelu_fast(rowv[1][e + 1] + conv);
            }
            __half2 h = __floats2half2_rn(f[0], f[1]);
            ow[t] = *reinterpret_cast<unsigned*>(&h);
        }
        dst[(r + 8) * 14 + 1 + v4] = make_uint4(ow[0], ow[1], ow[2], ow[3]);
    }
}

// ---- Kernel B: preprocess z -> ZA (A-fragment order) ---------------------------
__global__ __launch_bounds__(256) void prep_z(const float* __restrict__ z,
                                              const float* __restrict__ wz,
                                              const float* __restrict__ bz) {
    int bc = blockIdx.x;
    int c  = bc & 63;
    __shared__ float sp[18 * 18];

    for (int i = threadIdx.x; i < 18 * 18; i += 256) sp[i] = 0.0f;
    __syncthreads();

    int t = threadIdx.x;
    int p = t >> 4, q = t & 15;
    sp[(p + 1) * 18 + (q + 1)] = z[(size_t)bc * 256 + t];
    __syncthreads();

    float conv = __ldg(bz + c);
#pragma unroll
    for (int di = 0; di < 3; ++di)
#pragma unroll
        for (int dj = 0; dj < 3; ++dj)
            conv = fmaf(__ldg(wz + c * 9 + di * 3 + dj), sp[(p + di) * 18 + (q + dj)], conv);
    float val = gelu_fast(sp[(p + 1) * 18 + (q + 1)] + conv);

    int lane = ((p & 7) << 2) | ((q & 7) >> 1);
    int reg  = ((p >> 3) & 1) | (((q >> 3) & 1) << 1);
    int h    = q & 1;
    reinterpret_cast<__half*>(ZA)[((size_t)bc * 32 + lane) * 8 + reg * 2 + h] =
        __float2half(val);
}

// ---- Kernel Z: zero-init out ----------------------------------------------------
__global__ __launch_bounds__(256) void zero_out(float* __restrict__ out, int n4) {
    int t = blockIdx.x * 256 + threadIdx.x;
    float4 z4 = make_float4(0.f, 0.f, 0.f, 0.f);
    if (t < n4) reinterpret_cast<float4*>(out)[t] = z4;
}

// ---- Kernel C: correlation GEMM + fused scatter epilogue ------------------------
// Grid (24, 64): rows r0=8+4bx .. r0+3, warp w handles row r0+w, all 13 j-tiles.
__global__ __launch_bounds__(128) void corr(float* __restrict__ out) {
    extern __shared__ unsigned sq[];   // [row(4)][c(64)][word(64)] = 65536 B
    int r0 = 8 + 4 * blockIdx.x, b = blockIdx.y;
    int tid = threadIdx.x, lane = tid & 31, w = tid >> 5;
    int r = r0 + w;

    // Stage 4 rows: zero-fill words 56..63. Plane = 1568 uint4, row = 14 uint4.
    for (int t = tid; t < 4096; t += 128) {
        int row = t >> 10, g = t & 1023, c = g >> 4, v = g & 15;
        uint4 d = make_uint4(0u, 0u, 0u, 0u);
        if (v < 14)
            d = __ldg(reinterpret_cast<const uint4*>(XG) +
                      (size_t)(b * 64 + c) * 1568 + (size_t)(r0 + row) * 14 + v);
        reinterpret_cast<uint4*>(sq)[t] = d;
    }
    __syncthreads();

    // Per-lane B-frag addressing: element index e = nj + q0, word base = e>>1,
    // shift = (e&1)*16. Tile t: b0 = halves(8t+e, 8t+e+1), b1 = halves(8t+8+e,..).
    int nj = lane >> 2;
    int q0 = (lane & 3) << 1;
    int e  = nj + q0;                          // 0..13
    int eoff = e >> 1;                         // 0..6
    unsigned sh = (unsigned)((e & 1) << 4);    // funnel shift: 0 or 16
    const unsigned* base_row = sq + (w << 12); // w * 4096 words

    const uint4* zp = reinterpret_cast<const uint4*>(ZA) + (size_t)b * 64 * 32 + lane;

    float facc[13][4];
#pragma unroll
    for (int t = 0; t < 13; ++t)
#pragma unroll
        for (int k = 0; k < 4; ++k) facc[t][k] = 0.0f;

    unsigned hacc[13][2];
#pragma unroll
    for (int t = 0; t < 13; ++t) { hacc[t][0] = 0u; hacc[t][1] = 0u; }

    uint4 a = __ldg(zp);
#pragma unroll 1
    for (int cb = 0; cb < 8; ++cb) {
#pragma unroll
        for (int ci = 0; ci < 8; ++ci) {
            int c = 8 * cb + ci;
            uint4 an = __ldg(zp + (c + 1) * 32);   // ZA padded: safe at c=63
            const unsigned* bc = base_row + (c << 6) + eoff;
            // Rolling pair chain: pair k covers words {4k, 4k+1};
            // tile t uses pair t (b0) and pair t+1 (b1). Max word 4*13+1+6=59<64.
            unsigned cw0 = bc[0], cw1 = bc[1];
#pragma unroll
            for (int t = 0; t < 13; ++t) {
                unsigned nw0 = bc[4 * t + 4], nw1 = bc[4 * t + 5];
                unsigned b0 = __funnelshift_r(cw0, cw1, sh);
                unsigned b1 = __funnelshift_r(nw0, nw1, sh);
                asm volatile(
                    "mma.sync.aligned.m16n8k16.row.col.f16.f16.f16.f16 "
                    "{%0,%1}, {%2,%3,%4,%5}, {%6,%7}, {%0,%1};"
                    : "+r"(hacc[t][0]), "+r"(hacc[t][1])
                    : "r"(a.x), "r"(a.y), "r"(a.z), "r"(a.w), "r"(b0), "r"(b1));
                cw0 = nw0; cw1 = nw1;
            }
            a = an;
        }
        // Flush f16 fragments into fp32 accumulators (every 8 c)
#pragma unroll
        for (int t = 0; t < 13; ++t) {
            __half2 h0 = *reinterpret_cast<__half2*>(&hacc[t][0]);
            __half2 h1 = *reinterpret_cast<__half2*>(&hacc[t][1]);
            float2 f0 = __half22float2(h0);
            float2 f1 = __half22float2(h1);
            facc[t][0] += f0.x; facc[t][1] += f0.y;
            facc[t][2] += f1.x; facc[t][3] += f1.y;
            hacc[t][0] = 0u; hacc[t][1] = 0u;
        }
    }

    // Fused epilogue: out[b, r-p, j] += 0.001 * H[p][j]
    int p0 = lane >> 2, jn = (lane & 3) << 1;
    float* ob = out + (size_t)b * 9409;
    int i_hi = r - p0;        // p = p0
    int i_lo = i_hi - 8;      // p = p0 + 8
#pragma unroll
    for (int t = 0; t < 13; ++t) {
        int j = t * 8 + jn;
        bool j0 = (j <= 96), j1 = (j < 96);
        if (i_hi <= 96) {
            if (j0) red_add(ob + i_hi * 97 + j,     facc[t][0] * 0.001f);
            if (j1) red_add(ob + i_hi * 97 + j + 1, facc[t][1] * 0.001f);
        }
        if (i_lo >= 0) {
            if (j0) red_add(ob + i_lo * 97 + j,     facc[t][2] * 0.001f);
            if (j1) red_add(ob + i_lo * 97 + j + 1, facc[t][3] * 0.001f);
        }
    }
}

// ---- launch -----------------------------------------------------------------------
extern "C" void kernel_launch(void* const* d_in, const int* in_sizes, int n_in,
                              void* d_out, int out_size) {
    const float* z  = (const float*)d_in[0];
    const float* x  = (const float*)d_in[1];
    const float* wz = (const float*)d_in[2];
    const float* bz = (const float*)d_in[3];
    const float* wx = (const float*)d_in[4];
    const float* bx = (const float*)d_in[5];
    float* out = (float*)d_out;

    const int SMEM = 65536;
    cudaFuncSetAttribute(corr, cudaFuncAttributeMaxDynamicSharedMemorySize, SMEM);

    int n4 = out_size / 4;  // 150544
    zero_out<<<(n4 + 255) / 256, 256>>>(out, n4);
    prep_x<<<4096, 192>>>(x, wx, bx);
    prep_z<<<4096, 256>>>(z, wz, bz);
    corr<<<dim3(24, 64), 128, SMEM>>>(out);
}

// round 13
// speedup vs baseline: 1.0810x; 1.0317x over previous
#include <cuda_runtime.h>
#include <cuda_fp16.h>
#include <math.h>

// ---------------------------------------------------------------------------
// SiamFC head, round 13: R12 + depth-4 A-fragment prefetch.
//   H[b,r,j,p] = sum_{c,q} x'[b,c,r-8,j+q-8] * z'[b,c,p,q]   (HMMA f16-acc)
//   out[b,i,j] = 0.001 * sum_p H[b,i+p,j,p]                  (fused via RED)
// corr: 4 rows/CTA (warp = row), 13 j-tiles/warp; rolling-pair B-frag loads
// (28 LDS.32/warp-c); A-fragments prefetched 4 c-steps ahead (covers L2 lat);
// f16->f32 flush every 8 c; RED scatter epilogue.
// ---------------------------------------------------------------------------

__device__ __align__(16) unsigned XG[64 * 64 * 112 * 56];     // x' fp16 half2 words
__device__ __align__(16) unsigned ZA[(64 * 64 + 8) * 128];    // z' A-frag order (+pad)

// Fast exact-GELU: erf via Abramowitz-Stegun 7.1.26 (|err| <= 1.5e-7 abs).
__device__ __forceinline__ float gelu_fast(float v) {
    float s = fabsf(v) * 0.70710678118654752f;
    float t = __frcp_rn(fmaf(0.3275911f, s, 1.0f));
    float p = fmaf(1.061405429f, t, -1.453152027f);
    p = fmaf(p, t, 1.421413741f);
    p = fmaf(p, t, -0.284496736f);
    p = fmaf(p, t, 0.254829592f);
    p = p * t;
    float erfabs = fmaf(-p, __expf(-s * s), 1.0f);
    float erfs = copysignf(erfabs, v);
    return 0.5f * v * (1.0f + erfs);
}

__device__ __forceinline__ void red_add(float* p, float v) {
    asm volatile("red.global.add.f32 [%0], %1;" :: "l"(p), "f"(v) : "memory");
}

// ---- Kernel A: preprocess x -> XG ---------------------------------------------
__global__ __launch_bounds__(192) void prep_x(const float* __restrict__ x,
                                              const float* __restrict__ wx,
                                              const float* __restrict__ bx) {
    int bc = blockIdx.x;        // b*64 + c
    int c  = bc & 63;
    int tid = threadIdx.x;
    __shared__ __align__(16) float sp[98 * 100];

    float4 z4 = make_float4(0.f, 0.f, 0.f, 0.f);
    for (int i = tid; i < 2450; i += 192) reinterpret_cast<float4*>(sp)[i] = z4;
    __syncthreads();

    {
        int col = (tid < 96) ? tid : tid - 96;
        int rp  = (tid < 96) ? 0 : 1;
        const float* xp = x + (size_t)bc * 9216;
        for (int k = 0; k < 48; ++k) {
            int r = 2 * k + rp;
            sp[(r + 1) * 100 + (col + 1)] = xp[r * 96 + col];
        }
    }
    __syncthreads();

    float w[9];
#pragma unroll
    for (int k = 0; k < 9; ++k) w[k] = __ldg(wx + c * 9 + k);
    float bias = __ldg(bx + c);

    int v4 = tid % 12;
    int r0 = tid / 12;
    int xc0 = v4 * 8;

    uint4* dst = reinterpret_cast<uint4*>(XG + (size_t)bc * (112 * 56));
#pragma unroll 1
    for (int it = 0; it < 6; ++it) {
        int r = r0 + 16 * it;
        float rowv[3][12];
#pragma unroll
        for (int di = 0; di < 3; ++di) {
            const float4* src = reinterpret_cast<const float4*>(sp + (r + di) * 100 + xc0);
            float4 A = src[0], B = src[1], C = src[2];
            rowv[di][0] = A.x; rowv[di][1] = A.y; rowv[di][2]  = A.z; rowv[di][3]  = A.w;
            rowv[di][4] = B.x; rowv[di][5] = B.y; rowv[di][6]  = B.z; rowv[di][7]  = B.w;
            rowv[di][8] = C.x; rowv[di][9] = C.y; rowv[di][10] = C.z; rowv[di][11] = C.w;
        }
        unsigned ow[4];
#pragma unroll
        for (int t = 0; t < 4; ++t) {
            float f[2];
#pragma unroll
            for (int u = 0; u < 2; ++u) {
                int e = 2 * t + u;
                float conv = bias;
#pragma unroll
                for (int di = 0; di < 3; ++di)
#pragma unroll
                    for (int dj = 0; dj < 3; ++dj)
                        conv = fmaf(w[di * 3 + dj], rowv[di][e + dj], conv);
                f[u] = gelu_fast(rowv[1][e + 1] + conv);
            }
            __half2 h = __floats2half2_rn(f[0], f[1]);
            ow[t] = *reinterpret_cast<unsigned*>(&h);
        }
        dst[(r + 8) * 14 + 1 + v4] = make_uint4(ow[0], ow[1], ow[2], ow[3]);
    }
}

// ---- Kernel B: preprocess z -> ZA (A-fragment order) ---------------------------
__global__ __launch_bounds__(256) void prep_z(const float* __restrict__ z,
                                              const float* __restrict__ wz,
                                              const float* __restrict__ bz) {
    int bc = blockIdx.x;
    int c  = bc & 63;
    __shared__ float sp[18 * 18];

    for (int i = threadIdx.x; i < 18 * 18; i += 256) sp[i] = 0.0f;
    __syncthreads();

    int t = threadIdx.x;
    int p = t >> 4, q = t & 15;
    sp[(p + 1) * 18 + (q + 1)] = z[(size_t)bc * 256 + t];
    __syncthreads();

    float conv = __ldg(bz + c);
#pragma unroll
    for (int di = 0; di < 3; ++di)
#pragma unroll
        for (int dj = 0; dj < 3; ++dj)
            conv = fmaf(__ldg(wz + c * 9 + di * 3 + dj), sp[(p + di) * 18 + (q + dj)], conv);
    float val = gelu_fast(sp[(p + 1) * 18 + (q + 1)] + conv);

    int lane = ((p & 7) << 2) | ((q & 7) >> 1);
    int reg  = ((p >> 3) & 1) | (((q >> 3) & 1) << 1);
    int h    = q & 1;
    reinterpret_cast<__half*>(ZA)[((size_t)bc * 32 + lane) * 8 + reg * 2 + h] =
        __float2half(val);
}

// ---- Kernel Z: zero-init out ----------------------------------------------------
__global__ __launch_bounds__(256) void zero_out(float* __restrict__ out, int n4) {
    int t = blockIdx.x * 256 + threadIdx.x;
    float4 z4 = make_float4(0.f, 0.f, 0.f, 0.f);
    if (t < n4) reinterpret_cast<float4*>(out)[t] = z4;
}

// ---- Kernel C: correlation GEMM + fused scatter epilogue ------------------------
// Grid (24, 64): rows r0=8+4bx .. r0+3, warp w handles row r0+w, all 13 j-tiles.
__global__ __launch_bounds__(128) void corr(float* __restrict__ out) {
    extern __shared__ unsigned sq[];   // [row(4)][c(64)][word(64)] = 65536 B
    int r0 = 8 + 4 * blockIdx.x, b = blockIdx.y;
    int tid = threadIdx.x, lane = tid & 31, w = tid >> 5;
    int r = r0 + w;

    // Stage 4 rows: zero-fill words 56..63. Plane = 1568 uint4, row = 14 uint4.
    for (int t = tid; t < 4096; t += 128) {
        int row = t >> 10, g = t & 1023, c = g >> 4, v = g & 15;
        uint4 d = make_uint4(0u, 0u, 0u, 0u);
        if (v < 14)
            d = __ldg(reinterpret_cast<const uint4*>(XG) +
                      (size_t)(b * 64 + c) * 1568 + (size_t)(r0 + row) * 14 + v);
        reinterpret_cast<uint4*>(sq)[t] = d;
    }
    __syncthreads();

    // Per-lane B-frag addressing: element index e = nj + q0, word base = e>>1,
    // shift = (e&1)*16. Tile t: b0 = halves(8t+e, 8t+e+1), b1 = halves(8t+8+e,..).
    int nj = lane >> 2;
    int q0 = (lane & 3) << 1;
    int e  = nj + q0;                          // 0..13
    int eoff = e >> 1;                         // 0..6
    unsigned sh = (unsigned)((e & 1) << 4);    // funnel shift: 0 or 16
    const unsigned* base_row = sq + (w << 12); // w * 4096 words

    const uint4* zp = reinterpret_cast<const uint4*>(ZA) + (size_t)b * 64 * 32 + lane;

    float facc[13][4];
#pragma unroll
    for (int t = 0; t < 13; ++t)
#pragma unroll
        for (int k = 0; k < 4; ++k) facc[t][k] = 0.0f;

    unsigned hacc[13][2];
#pragma unroll
    for (int t = 0; t < 13; ++t) { hacc[t][0] = 0u; hacc[t][1] = 0u; }

    // Depth-4 A-fragment prefetch pipeline (covers ~234cyc L2 latency with
    // ~4x104cyc of MMA work in flight). ZA padded by 8 blocks -> c+4 safe.
    uint4 abuf[4];
#pragma unroll
    for (int i = 0; i < 4; ++i) abuf[i] = __ldg(zp + i * 32);

#pragma unroll 1
    for (int cb = 0; cb < 16; ++cb) {
#pragma unroll
        for (int ci = 0; ci < 4; ++ci) {
            int c = 4 * cb + ci;
            uint4 a = abuf[ci];
            abuf[ci] = __ldg(zp + (c + 4) * 32);   // prefetch c+4
            const unsigned* bc = base_row + (c << 6) + eoff;
            // Rolling pair chain: tile t uses pair t (b0) and pair t+1 (b1).
            unsigned cw0 = bc[0], cw1 = bc[1];
#pragma unroll
            for (int t = 0; t < 13; ++t) {
                unsigned nw0 = bc[4 * t + 4], nw1 = bc[4 * t + 5];
                unsigned b0 = __funnelshift_r(cw0, cw1, sh);
                unsigned b1 = __funnelshift_r(nw0, nw1, sh);
                asm volatile(
                    "mma.sync.aligned.m16n8k16.row.col.f16.f16.f16.f16 "
                    "{%0,%1}, {%2,%3,%4,%5}, {%6,%7}, {%0,%1};"
                    : "+r"(hacc[t][0]), "+r"(hacc[t][1])
                    : "r"(a.x), "r"(a.y), "r"(a.z), "r"(a.w), "r"(b0), "r"(b1));
                cw0 = nw0; cw1 = nw1;
            }
        }
        if (cb & 1) {
            // Flush f16 fragments into fp32 accumulators (every 8 c)
#pragma unroll
            for (int t = 0; t < 13; ++t) {
                __half2 h0 = *reinterpret_cast<__half2*>(&hacc[t][0]);
                __half2 h1 = *reinterpret_cast<__half2*>(&hacc[t][1]);
                float2 f0 = __half22float2(h0);
                float2 f1 = __half22float2(h1);
                facc[t][0] += f0.x; facc[t][1] += f0.y;
                facc[t][2] += f1.x; facc[t][3] += f1.y;
                hacc[t][0] = 0u; hacc[t][1] = 0u;
            }
        }
    }

    // Fused epilogue: out[b, r-p, j] += 0.001 * H[p][j]
    int p0 = lane >> 2, jn = (lane & 3) << 1;
    float* ob = out + (size_t)b * 9409;
    int i_hi = r - p0;        // p = p0
    int i_lo = i_hi - 8;      // p = p0 + 8
#pragma unroll
    for (int t = 0; t < 13; ++t) {
        int j = t * 8 + jn;
        bool j0 = (j <= 96), j1 = (j < 96);
        if (i_hi <= 96) {
            if (j0) red_add(ob + i_hi * 97 + j,     facc[t][0] * 0.001f);
            if (j1) red_add(ob + i_hi * 97 + j + 1, facc[t][1] * 0.001f);
        }
        if (i_lo >= 0) {
            if (j0) red_add(ob + i_lo * 97 + j,     facc[t][2] * 0.001f);
            if (j1) red_add(ob + i_lo * 97 + j + 1, facc[t][3] * 0.001f);
        }
    }
}

// ---- launch -----------------------------------------------------------------------
extern "C" void kernel_launch(void* const* d_in, const int* in_sizes, int n_in,
                              void* d_out, int out_size) {
    const float* z  = (const float*)d_in[0];
    const float* x  = (const float*)d_in[1];
    const float* wz = (const float*)d_in[2];
    const float* bz = (const float*)d_in[3];
    const float* wx = (const float*)d_in[4];
    const float* bx = (const float*)d_in[5];
    float* out = (float*)d_out;

    const int SMEM = 65536;
    cudaFuncSetAttribute(corr, cudaFuncAttributeMaxDynamicSharedMemorySize, SMEM);

    int n4 = out_size / 4;  // 150544
    zero_out<<<(n4 + 255) / 256, 256>>>(out, n4);
    prep_x<<<4096, 192>>>(x, wx, bx);
    prep_z<<<4096, 256>>>(z, wz, bz);
    corr<<<dim3(24, 64), 128, SMEM>>>(out);
}